// round 4
// baseline (speedup 1.0000x reference)
#include <cuda_runtime.h>

#define B_TOT 512
#define T_LEN 1000
#define IN_D  26
#define H1_D  64
#define H2_D  32
#define F1_D  16
#define OUT_D 10

#define S_PER 4                  // samples per block
#define NBLK  (B_TOT / S_PER)    // 128 blocks -> one wave on 148 SMs
#define NTHR  384                // 256 L1 gate rows + 128 L2 gate rows
#define CHUNK 16                 // x time-chunk staged in smem

__device__ __forceinline__ float sigm(float xv) {
    float e = __expf(-xv);
    return __fdividef(1.0f, 1.0f + e);
}
// overflow-safe tanh: sign(x) * (1 - 2/(exp(2|x|)+1)); exp->inf gives 2/inf=0 -> +-1
__device__ __forceinline__ float tanh_(float xv) {
    float a = fabsf(xv);
    float e = __expf(2.0f * a);
    float r = 1.0f - __fdividef(2.0f, e + 1.0f);
    return copysignf(r, xv);
}

__global__ __launch_bounds__(NTHR, 1)
void lstm_fused(const float* __restrict__ x,
                const float* __restrict__ w_ih1, const float* __restrict__ w_hh1,
                const float* __restrict__ b_ih1, const float* __restrict__ b_hh1,
                const float* __restrict__ w_ih2, const float* __restrict__ w_hh2,
                const float* __restrict__ b_ih2, const float* __restrict__ b_hh2,
                const float* __restrict__ w_fc1, const float* __restrict__ b_fc1,
                const float* __restrict__ w_fc2, const float* __restrict__ b_fc2,
                float* __restrict__ out)
{
    __shared__ __align__(16) float h1s[S_PER][H1_D];        // h1(t-1) -> h1(t)
    __shared__ __align__(16) float h2s[S_PER][H2_D];        // h2(t-2) -> h2(t-1)
    __shared__ __align__(16) float g1s[S_PER][4 * H1_D];    // L1 gate pre-activations
    __shared__ __align__(16) float g2s[S_PER][4 * H2_D];    // L2 gate pre-activations
    __shared__ __align__(16) float xs [S_PER][CHUNK][28];   // x chunk, transposed, padded
    __shared__ __align__(16) float fcb[S_PER][F1_D];

    const int tid = threadIdx.x;
    const int b0  = blockIdx.x * S_PER;

    // zero states + xs (incl. pad cols 26,27 — must be 0, they multiply pad weights)
    for (int i = tid; i < S_PER * H1_D; i += NTHR)       (&h1s[0][0])[i] = 0.f;
    for (int i = tid; i < S_PER * H2_D; i += NTHR)       (&h2s[0][0])[i] = 0.f;
    for (int i = tid; i < S_PER * CHUNK * 28; i += NTHR) (&xs[0][0][0])[i] = 0.f;

    // ---- per-thread register weights: one gate row per lane ----
    // L1 lane (tid<256):  w[0..27]=w_ih row (padded), w[28..91]=w_hh row
    // L2 lane (tid>=256): w[0..63]=w_ih2 row, w[64..95]=w_hh2 row
    float w[96];
    float bias;
    float cst = 0.f;    // cell state owned by this thread's update role
    if (tid < 256) {
        const int r = tid;
        #pragma unroll
        for (int i = 0; i < 26; i++) w[i] = w_ih1[r * 26 + i];
        w[26] = 0.f; w[27] = 0.f;
        #pragma unroll
        for (int k = 0; k < 64; k++) w[28 + k] = w_hh1[r * 64 + k];
        w[92] = 0.f; w[93] = 0.f; w[94] = 0.f; w[95] = 0.f;
        bias = b_ih1[r] + b_hh1[r];
    } else {
        const int r = tid - 256;
        #pragma unroll
        for (int k = 0; k < 64; k++) w[k] = w_ih2[r * 64 + k];
        #pragma unroll
        for (int k = 0; k < 32; k++) w[64 + k] = w_hh2[r * 32 + k];
        bias = b_ih2[r] + b_hh2[r];
    }
    __syncthreads();

    // ---- time loop, L2 pipelined one step behind L1; t==T_LEN is the drain ----
    for (int t = 0; t <= T_LEN; t++) {
        const int tc = t & (CHUNK - 1);

        if (tc == 0 && t < T_LEN) {
            // stage x[:, :, t .. t+CHUNK) into smem (transposed to [s][t][i])
            if (tid < S_PER * IN_D) {
                const int s = tid / IN_D;
                const int i = tid % IN_D;
                const float* gp = x + ((size_t)(b0 + s) * IN_D + i) * T_LEN + t;
                const int rem = T_LEN - t;
                if (rem >= CHUNK) {
                    const float4* gp4 = (const float4*)gp;   // 16B aligned: 4000|16, t%16==0
                    #pragma unroll
                    for (int j4 = 0; j4 < CHUNK / 4; j4++) {
                        float4 v = gp4[j4];
                        xs[s][j4 * 4 + 0][i] = v.x;
                        xs[s][j4 * 4 + 1][i] = v.y;
                        xs[s][j4 * 4 + 2][i] = v.z;
                        xs[s][j4 * 4 + 3][i] = v.w;
                    }
                } else {
                    for (int j = 0; j < rem; j++) xs[s][j][i] = gp[j];
                }
            }
            __syncthreads();
        }

        // ---- PHASE A: gate dot-products (all 12 warps busy) ----
        if (tid < 256) {
            if (t < T_LEN) {                    // L1 gates(t) from x(t), h1(t-1)
                const int row = tid;
                #pragma unroll
                for (int s = 0; s < S_PER; s++) {
                    float acc = bias;
                    const float4* xv = (const float4*)xs[s][tc];
                    #pragma unroll
                    for (int q = 0; q < 7; q++) {
                        float4 v = xv[q];
                        acc += w[4*q+0]*v.x; acc += w[4*q+1]*v.y;
                        acc += w[4*q+2]*v.z; acc += w[4*q+3]*v.w;
                    }
                    const float4* hv = (const float4*)h1s[s];
                    #pragma unroll
                    for (int q = 0; q < 16; q++) {
                        float4 v = hv[q];
                        acc += w[28+4*q+0]*v.x; acc += w[28+4*q+1]*v.y;
                        acc += w[28+4*q+2]*v.z; acc += w[28+4*q+3]*v.w;
                    }
                    g1s[s][row] = acc;
                }
            }
        } else {
            if (t >= 1) {                       // L2 gates(t-1) from h1(t-1), h2(t-2)
                const int row = tid - 256;
                #pragma unroll
                for (int s = 0; s < S_PER; s++) {
                    float acc = bias;
                    const float4* hv = (const float4*)h1s[s];
                    #pragma unroll
                    for (int q = 0; q < 16; q++) {
                        float4 v = hv[q];
                        acc += w[4*q+0]*v.x; acc += w[4*q+1]*v.y;
                        acc += w[4*q+2]*v.z; acc += w[4*q+3]*v.w;
                    }
                    const float4* h2v = (const float4*)h2s[s];
                    #pragma unroll
                    for (int q = 0; q < 8; q++) {
                        float4 v = h2v[q];
                        acc += w[64+4*q+0]*v.x; acc += w[64+4*q+1]*v.y;
                        acc += w[64+4*q+2]*v.z; acc += w[64+4*q+3]*v.w;
                    }
                    g2s[s][row] = acc;
                }
            }
        }
        __syncthreads();

        // ---- PHASE B: pointwise LSTM cell updates ----
        if (tid < 256) {
            if (t < T_LEN) {                    // update (s,u) of layer 1 -> h1(t)
                const int s = tid >> 6, u = tid & 63;
                float ig = sigm (g1s[s][u]);
                float fg = sigm (g1s[s][64  + u]);
                float gg = tanh_(g1s[s][128 + u]);
                float og = sigm (g1s[s][192 + u]);
                cst = fg * cst + ig * gg;
                h1s[s][u] = og * tanh_(cst);
            }
        } else {
            if (t >= 1) {                       // update (s,u) of layer 2 -> h2(t-1)
                const int q2 = tid - 256;
                const int s = q2 >> 5, u = q2 & 31;
                float ig = sigm (g2s[s][u]);
                float fg = sigm (g2s[s][32 + u]);
                float gg = tanh_(g2s[s][64 + u]);
                float og = sigm (g2s[s][96 + u]);
                cst = fg * cst + ig * gg;
                h2s[s][u] = og * tanh_(cst);
            }
        }
        __syncthreads();
    }

    // ---- FC head: h2(final) -> relu(fc1) -> fc2 ----
    if (tid < S_PER * F1_D) {
        const int s = tid / F1_D, j = tid % F1_D;
        float acc = b_fc1[j];
        #pragma unroll
        for (int k = 0; k < H2_D; k++) acc += w_fc1[j * H2_D + k] * h2s[s][k];
        fcb[s][j] = fmaxf(acc, 0.f);
    }
    __syncthreads();
    if (tid < S_PER * OUT_D) {
        const int s = tid / OUT_D, j = tid % OUT_D;
        float acc = b_fc2[j];
        #pragma unroll
        for (int k = 0; k < F1_D; k++) acc += w_fc2[j * F1_D + k] * fcb[s][k];
        out[(b0 + s) * OUT_D + j] = acc;
    }
}

extern "C" void kernel_launch(void* const* d_in, const int* in_sizes, int n_in,
                              void* d_out, int out_size)
{
    lstm_fused<<<NBLK, NTHR>>>(
        (const float*)d_in[0],                       // x
        (const float*)d_in[1],  (const float*)d_in[2],   // w_ih1, w_hh1
        (const float*)d_in[3],  (const float*)d_in[4],   // b_ih1, b_hh1
        (const float*)d_in[5],  (const float*)d_in[6],   // w_ih2, w_hh2
        (const float*)d_in[7],  (const float*)d_in[8],   // b_ih2, b_hh2
        (const float*)d_in[9],  (const float*)d_in[10],  // w_fc1, b_fc1
        (const float*)d_in[11], (const float*)d_in[12],  // w_fc2, b_fc2
        (float*)d_out);
}

// round 5
// speedup vs baseline: 1.0307x; 1.0307x over previous
#include <cuda_runtime.h>

typedef unsigned long long ull;

#define B_TOT 512
#define T_LEN 1000
#define IN_D  26
#define H1_D  64
#define H2_D  32
#define F1_D  16
#define OUT_D 10

#define S_PER 4                  // samples per block
#define NBLK  (B_TOT / S_PER)    // 128 blocks -> one wave
#define NTHR  384                // 12 warps: 8x L1 (A/B halves), 4x L2 (A/B halves)
#define CHUNK 16

// ---- f32x2 packed helpers ----
__device__ __forceinline__ ull pk2(float lo, float hi) {
    ull r; asm("mov.b64 %0, {%1, %2};" : "=l"(r) : "f"(lo), "f"(hi)); return r;
}
__device__ __forceinline__ float2 unpk(ull v) {
    float2 r; asm("mov.b64 {%0, %1}, %2;" : "=f"(r.x), "=f"(r.y) : "l"(v)); return r;
}
__device__ __forceinline__ ull fma2(ull a, ull b, ull c) {
    ull d; asm("fma.rn.f32x2 %0, %1, %2, %3;" : "=l"(d) : "l"(a), "l"(b), "l"(c)); return d;
}

__device__ __forceinline__ float sigm(float xv) {
    float e = __expf(-xv);
    return __fdividef(1.0f, 1.0f + e);
}
__device__ __forceinline__ float tanh_(float xv) {
    float a = fabsf(xv);
    float e = __expf(2.0f * a);
    float r = 1.0f - __fdividef(2.0f, e + 1.0f);
    return copysignf(r, xv);
}
__device__ __forceinline__ float comp2(float2 v, int c) { return c ? v.y : v.x; }

__global__ __launch_bounds__(NTHR, 1)
void lstm_fused(const float* __restrict__ x,
                const float* __restrict__ w_ih1, const float* __restrict__ w_hh1,
                const float* __restrict__ b_ih1, const float* __restrict__ b_hh1,
                const float* __restrict__ w_ih2, const float* __restrict__ w_hh2,
                const float* __restrict__ b_ih2, const float* __restrict__ b_hh2,
                const float* __restrict__ w_fc1, const float* __restrict__ b_fc1,
                const float* __restrict__ w_fc2, const float* __restrict__ b_fc2,
                float* __restrict__ out)
{
    // duplicated-pair activation storage: each entry is {v, v} as 64-bit
    __shared__ __align__(16) ull    h1d[S_PER][H1_D];          // h1(t-1)
    __shared__ __align__(16) ull    h2d[S_PER][H2_D];          // h2(t-2)
    __shared__ __align__(16) ull    xsd[S_PER][CHUNK][28];     // x chunk, dup, padded
    // gate partial sums: [half][sample][row-pair] = {row 2p, row 2p+1}
    __shared__ __align__(16) float2 g1p[2][S_PER][128];
    __shared__ __align__(16) float2 g2p[2][S_PER][64];
    __shared__ __align__(16) float  fcb[S_PER][F1_D];

    const int tid = threadIdx.x;
    const int b0  = blockIdx.x * S_PER;

    for (int i = tid; i < S_PER * H1_D; i += NTHR)       (&h1d[0][0])[i] = 0ULL;
    for (int i = tid; i < S_PER * H2_D; i += NTHR)       (&h2d[0][0])[i] = 0ULL;
    for (int i = tid; i < S_PER * CHUNK * 28; i += NTHR) (&xsd[0][0][0])[i] = 0ULL;

    // ---- per-thread packed weights: 2 adjacent gate rows, half the dot ----
    // warps 0-3  (tid<128):   L1 half A: k = x[0..28) + h1[0..16)   (44 pairs)
    // warps 4-7  (tid<256):   L1 half B: k = h1[16..64)             (48 pairs)
    // warps 8-9  (tid<320):   L2 half A: k = h1[0..48)              (48 pairs)
    // warps 10-11(tid<384):   L2 half B: k = h1[48..64)+h2[0..32)   (48 pairs)
    ull w2[48];
    ull bias2 = 0ULL;
    float cst = 0.f;     // cell state for this thread's phase-B role

    if (tid < 128) {
        const int r0 = 2 * tid, r1 = r0 + 1;
        #pragma unroll
        for (int k = 0; k < 28; k++) {
            float a = (k < 26) ? w_ih1[r0 * 26 + k] : 0.f;
            float b = (k < 26) ? w_ih1[r1 * 26 + k] : 0.f;
            w2[k] = pk2(a, b);
        }
        #pragma unroll
        for (int k = 0; k < 16; k++)
            w2[28 + k] = pk2(w_hh1[r0 * 64 + k], w_hh1[r1 * 64 + k]);
        w2[44] = 0ULL; w2[45] = 0ULL; w2[46] = 0ULL; w2[47] = 0ULL;
        bias2 = pk2(b_ih1[r0] + b_hh1[r0], b_ih1[r1] + b_hh1[r1]);
    } else if (tid < 256) {
        const int p = tid - 128, r0 = 2 * p, r1 = r0 + 1;
        #pragma unroll
        for (int k = 0; k < 48; k++)
            w2[k] = pk2(w_hh1[r0 * 64 + 16 + k], w_hh1[r1 * 64 + 16 + k]);
    } else if (tid < 320) {
        const int p = tid - 256, r0 = 2 * p, r1 = r0 + 1;
        #pragma unroll
        for (int k = 0; k < 48; k++)
            w2[k] = pk2(w_ih2[r0 * 64 + k], w_ih2[r1 * 64 + k]);
        bias2 = pk2(b_ih2[r0] + b_hh2[r0], b_ih2[r1] + b_hh2[r1]);
    } else {
        const int p = tid - 320, r0 = 2 * p, r1 = r0 + 1;
        #pragma unroll
        for (int k = 0; k < 16; k++)
            w2[k] = pk2(w_ih2[r0 * 64 + 48 + k], w_ih2[r1 * 64 + 48 + k]);
        #pragma unroll
        for (int k = 0; k < 32; k++)
            w2[16 + k] = pk2(w_hh2[r0 * 32 + k], w_hh2[r1 * 32 + k]);
    }
    __syncthreads();

    // ---- time loop; L2 one step behind L1; t==T_LEN is the drain ----
    for (int t = 0; t <= T_LEN; t++) {
        const int tc = t & (CHUNK - 1);

        if (tc == 0 && t < T_LEN) {
            if (tid < S_PER * IN_D) {
                const int s = tid / IN_D;
                const int i = tid % IN_D;
                const float* gp = x + ((size_t)(b0 + s) * IN_D + i) * T_LEN + t;
                const int rem = T_LEN - t;
                if (rem >= CHUNK) {
                    const float4* gp4 = (const float4*)gp;   // aligned: t%16==0, row=4000B
                    #pragma unroll
                    for (int j4 = 0; j4 < CHUNK / 4; j4++) {
                        float4 v = gp4[j4];
                        xsd[s][j4 * 4 + 0][i] = pk2(v.x, v.x);
                        xsd[s][j4 * 4 + 1][i] = pk2(v.y, v.y);
                        xsd[s][j4 * 4 + 2][i] = pk2(v.z, v.z);
                        xsd[s][j4 * 4 + 3][i] = pk2(v.w, v.w);
                    }
                } else {
                    for (int j = 0; j < rem; j++) xsd[s][j][i] = pk2(gp[j], gp[j]);
                }
            }
            __syncthreads();
        }

        // ---- PHASE A: packed gate dot-products ----
        if (tid < 128) {
            if (t < T_LEN) {                           // L1 half A
                const int p = tid;
                #pragma unroll
                for (int s = 0; s < S_PER; s++) {
                    ull acc = bias2;
                    const ull* xv = xsd[s][tc];
                    #pragma unroll
                    for (int k = 0; k < 28; k++) acc = fma2(w2[k], xv[k], acc);
                    const ull* hv = h1d[s];
                    #pragma unroll
                    for (int k = 0; k < 16; k++) acc = fma2(w2[28 + k], hv[k], acc);
                    g1p[0][s][p] = unpk(acc);
                }
            }
        } else if (tid < 256) {
            if (t < T_LEN) {                           // L1 half B
                const int p = tid - 128;
                #pragma unroll
                for (int s = 0; s < S_PER; s++) {
                    ull acc = 0ULL;
                    const ull* hv = h1d[s];
                    #pragma unroll
                    for (int k = 0; k < 48; k++) acc = fma2(w2[k], hv[16 + k], acc);
                    g1p[1][s][p] = unpk(acc);
                }
            }
        } else if (tid < 320) {
            if (t >= 1) {                              // L2 half A (gates for t-1)
                const int p = tid - 256;
                #pragma unroll
                for (int s = 0; s < S_PER; s++) {
                    ull acc = bias2;
                    const ull* hv = h1d[s];
                    #pragma unroll
                    for (int k = 0; k < 48; k++) acc = fma2(w2[k], hv[k], acc);
                    g2p[0][s][p] = unpk(acc);
                }
            }
        } else {
            if (t >= 1) {                              // L2 half B
                const int p = tid - 320;
                #pragma unroll
                for (int s = 0; s < S_PER; s++) {
                    ull acc = 0ULL;
                    const ull* hv = h1d[s];
                    #pragma unroll
                    for (int k = 0; k < 16; k++) acc = fma2(w2[k], hv[48 + k], acc);
                    const ull* h2v = h2d[s];
                    #pragma unroll
                    for (int k = 0; k < 32; k++) acc = fma2(w2[16 + k], h2v[k], acc);
                    g2p[1][s][p] = unpk(acc);
                }
            }
        }
        __syncthreads();

        // ---- PHASE B: pointwise cell updates (combine the two halves) ----
        if (tid < 256) {
            if (t < T_LEN) {                           // layer-1 unit update
                const int s = tid >> 6, u = tid & 63;
                const int pi = u >> 1, c = u & 1;
                float gi = comp2(g1p[0][s][pi],      c) + comp2(g1p[1][s][pi],      c);
                float gf = comp2(g1p[0][s][32 + pi], c) + comp2(g1p[1][s][32 + pi], c);
                float gg = comp2(g1p[0][s][64 + pi], c) + comp2(g1p[1][s][64 + pi], c);
                float go = comp2(g1p[0][s][96 + pi], c) + comp2(g1p[1][s][96 + pi], c);
                float ig = sigm(gi), fg = sigm(gf), g = tanh_(gg), og = sigm(go);
                cst = fg * cst + ig * g;
                float h = og * tanh_(cst);
                h1d[s][u] = pk2(h, h);
            }
        } else {
            if (t >= 1) {                              // layer-2 unit update
                const int q = tid - 256;
                const int s = q >> 5, u = q & 31;
                const int pi = u >> 1, c = u & 1;
                float gi = comp2(g2p[0][s][pi],      c) + comp2(g2p[1][s][pi],      c);
                float gf = comp2(g2p[0][s][16 + pi], c) + comp2(g2p[1][s][16 + pi], c);
                float gg = comp2(g2p[0][s][32 + pi], c) + comp2(g2p[1][s][32 + pi], c);
                float go = comp2(g2p[0][s][48 + pi], c) + comp2(g2p[1][s][48 + pi], c);
                float ig = sigm(gi), fg = sigm(gf), g = tanh_(gg), og = sigm(go);
                cst = fg * cst + ig * g;
                float h = og * tanh_(cst);
                h2d[s][u] = pk2(h, h);
            }
        }
        __syncthreads();
    }

    // ---- FC head ----
    if (tid < S_PER * F1_D) {
        const int s = tid / F1_D, j = tid % F1_D;
        float acc = b_fc1[j];
        #pragma unroll
        for (int k = 0; k < H2_D; k++) acc += w_fc1[j * H2_D + k] * unpk(h2d[s][k]).x;
        fcb[s][j] = fmaxf(acc, 0.f);
    }
    __syncthreads();
    if (tid < S_PER * OUT_D) {
        const int s = tid / OUT_D, j = tid % OUT_D;
        float acc = b_fc2[j];
        #pragma unroll
        for (int k = 0; k < F1_D; k++) acc += w_fc2[j * F1_D + k] * fcb[s][k];
        out[(b0 + s) * OUT_D + j] = acc;
    }
}

extern "C" void kernel_launch(void* const* d_in, const int* in_sizes, int n_in,
                              void* d_out, int out_size)
{
    lstm_fused<<<NBLK, NTHR>>>(
        (const float*)d_in[0],
        (const float*)d_in[1],  (const float*)d_in[2],
        (const float*)d_in[3],  (const float*)d_in[4],
        (const float*)d_in[5],  (const float*)d_in[6],
        (const float*)d_in[7],  (const float*)d_in[8],
        (const float*)d_in[9],  (const float*)d_in[10],
        (const float*)d_in[11], (const float*)d_in[12],
        (float*)d_out);
}